// round 17
// baseline (speedup 1.0000x reference)
#include <cuda_runtime.h>
#include <cuda_bf16.h>
#include <cstdint>

#define BATCH 4
#define CH 128
#define HH 96
#define WW 96
#define HW (HH*WW)
#define P98 9604           // 98*98 padded image
#define EPSBN 1e-5f
#define NTILES 72          // 9216 px / 128

#define WP 132
#define TMM 512            // threads per MMA kernel block

typedef unsigned long long u64;
typedef uint32_t u32;

// ===================== scalar fp32x2 helpers (conv_in) ======================
__device__ __forceinline__ void fma2(u64 &d, u64 a, u64 b) {
    asm("fma.rn.f32x2 %0, %1, %2, %0;" : "+l"(d) : "l"(a), "l"(b));
}
__device__ __forceinline__ u64 bc2(float x) {
    u64 r; asm("mov.b64 %0, {%1, %1};" : "=l"(r) : "f"(x)); return r;
}
__device__ __forceinline__ float2 unp2(u64 v) {
    float2 f; asm("mov.b64 {%0, %1}, %2;" : "=f"(f.x), "=f"(f.y) : "l"(v)); return f;
}
#define GSTEP(SROW, WROW) { \
    float4 xv = *(const float4*)(SROW); \
    ulonglong2 wA = *(const ulonglong2*)(WROW); \
    ulonglong2 wB = *(const ulonglong2*)((WROW)+4); \
    u64 xb0=bc2(xv.x), xb1=bc2(xv.y), xb2=bc2(xv.z), xb3=bc2(xv.w); \
    fma2(acc[0][0],wA.x,xb0); fma2(acc[0][1],wA.y,xb0); fma2(acc[0][2],wB.x,xb0); fma2(acc[0][3],wB.y,xb0); \
    fma2(acc[1][0],wA.x,xb1); fma2(acc[1][1],wA.y,xb1); fma2(acc[1][2],wB.x,xb1); fma2(acc[1][3],wB.y,xb1); \
    fma2(acc[2][0],wA.x,xb2); fma2(acc[2][1],wA.y,xb2); fma2(acc[2][2],wB.x,xb2); fma2(acc[2][3],wB.y,xb2); \
    fma2(acc[3][0],wA.x,xb3); fma2(acc[3][1],wA.y,xb3); fma2(acc[3][2],wB.x,xb3); fma2(acc[3][3],wB.y,xb3); }
#define ACC_INIT u64 acc[4][4]; _Pragma("unroll") for (int _i=0;_i<4;_i++) _Pragma("unroll") for(int _j=0;_j<4;_j++) acc[_i][_j]=0ull;

// ===================== mma.sync + ldmatrix + cp.async helpers ===============
#define SWZ(x) ((x) ^ ((((x) >> 8) & 7) << 4))

#define MMA_BF16(D, A, B0, B1) \
    asm volatile("mma.sync.aligned.m16n8k16.row.col.f32.bf16.bf16.f32 " \
        "{%0,%1,%2,%3}, {%4,%5,%6,%7}, {%8,%9}, {%0,%1,%2,%3};" \
        : "+f"((D)[0]), "+f"((D)[1]), "+f"((D)[2]), "+f"((D)[3]) \
        : "r"((A)[0]), "r"((A)[1]), "r"((A)[2]), "r"((A)[3]), "r"(B0), "r"(B1))

__device__ __forceinline__ void ldsm4(u32* r, u32 a) {
    asm volatile("ldmatrix.sync.aligned.m8n8.x4.shared.b16 {%0,%1,%2,%3}, [%4];"
        : "=r"(r[0]), "=r"(r[1]), "=r"(r[2]), "=r"(r[3]) : "r"(a));
}
__device__ __forceinline__ void ldsm2(u32* r, u32 a) {
    asm volatile("ldmatrix.sync.aligned.m8n8.x2.shared.b16 {%0,%1}, [%2];"
        : "=r"(r[0]), "=r"(r[1]) : "r"(a));
}

#define CP16(d, s)  asm volatile("cp.async.cg.shared.global [%0], [%1], 16;" :: "r"(d), "l"(s) : "memory")
#define CP_COMMIT() asm volatile("cp.async.commit_group;" ::: "memory")
#define CP_WAIT0()  asm volatile("cp.async.wait_group 0;" ::: "memory")

__device__ __forceinline__ u32 smem_to_u32(const void* p) {
    u32 a;
    asm("{ .reg .u64 t; cvta.to.shared.u64 t, %1; cvt.u32.u64 %0, t; }" : "=r"(a) : "l"(p));
    return a;
}
__device__ __forceinline__ void split2(float v, __nv_bfloat16 &h, __nv_bfloat16 &l) {
    h = __float2bfloat16(v);
    l = __float2bfloat16(v - __bfloat162float(h));
}

// smem layouts (each A buffer: hi 32K then lo 32K)
#define TD_A0   0
#define TD_A1   65536
#define TD_B    131072
#define SMEM_TD 196608     // tdef: A0,A1,B
#define TS_A0   0
#define TS_A1   65536
#define TS_B    131072
#define TS_BO0  196608
#define TS_BO1  208896
#define SMEM_TS 221184     // tstd: A0,A1,B,Bo0,Bo1
#define TO_A    0
#define TO_B    65536
#define SMEM_TO 131072     // tout

// ===================== scratch globals ======================================
__device__ float g_xp [BATCH*P98*CH];           // x_c padded NHWC fp32
__device__ __nv_bfloat16 g_xpH[BATCH*P98*CH];   // padded NHWC bf16 hi
__device__ __nv_bfloat16 g_xpL[BATCH*P98*CH];   // padded NHWC bf16 lo
__device__ float g_off[BATCH*18*HW];
__device__ __nv_bfloat16 g_wdH[9*16384], g_wdL[9*16384];
__device__ __nv_bfloat16 g_wsH[9*16384], g_wsL[9*16384];
__device__ __nv_bfloat16 g_woH[4*16384], g_woL[4*16384];
__device__ __nv_bfloat16 g_wfH[9*3072],  g_wfL[9*3072];   // offset conv weights (24 rows x 128)
__device__ __nv_bfloat16 g_a1H[BATCH*NTILES*16384], g_a1L[BATCH*NTILES*16384];
__device__ __nv_bfloat16 g_a2H[BATCH*NTILES*16384], g_a2L[BATCH*NTILES*16384];

// ===================== k_zero: clear padded buffers =========================
__global__ void k_zero() {
    size_t idx = (size_t)blockIdx.x*256 + threadIdx.x;
    size_t stride = (size_t)gridDim.x*256;
    for (size_t i = idx; i < (size_t)BATCH*P98*CH/4; i += stride)
        ((float4*)g_xp)[i] = make_float4(0.f,0.f,0.f,0.f);
    for (size_t i = idx; i < (size_t)BATCH*P98*CH/8; i += stride) {
        ((uint4*)g_xpH)[i] = make_uint4(0,0,0,0);
        ((uint4*)g_xpL)[i] = make_uint4(0,0,0,0);
    }
}

// ===================== k_prep: weight split + swizzled tiles ================
__global__ void k_prep(const float* __restrict__ wdef, const float* __restrict__ wstd,
                       const float* __restrict__ wout, const float* __restrict__ woff) {
    int idx = blockIdx.x * 256 + threadIdx.x;
    if (idx < 147456) {
        int n = idx / 16384, r = idx % 16384;
        int co = r >> 7, ci = r & 127;
        int off = SWZ(co*256 + ci*2);
        int dst = n*16384 + (off >> 1);
        int src = co*1152 + ci*9 + n;
        __nv_bfloat16 h, l;
        split2(wdef[src], h, l); g_wdH[dst] = h; g_wdL[dst] = l;
        split2(wstd[src], h, l); g_wsH[dst] = h; g_wsL[dst] = l;
    } else if (idx < 147456 + 65536) {
        int j = idx - 147456;
        int ci = j & 127, co = (j >> 7) & 127, kc = (j >> 14) & 1, z = (j >> 15) & 1;
        int off = SWZ(co*256 + ci*2);
        int dst = (z*2 + kc)*16384 + (off >> 1);
        __nv_bfloat16 h, l;
        split2(wout[(z*128 + co)*256 + kc*128 + ci], h, l);
        g_woH[dst] = h; g_woL[dst] = l;
    } else if (idx < 147456 + 65536 + 27648) {
        int j = idx - 147456 - 65536;
        int n = j / 3072, r = j % 3072;
        int co = r >> 7, ci = r & 127;        // co 0..23
        float v = (co < 18) ? woff[co*1152 + ci*9 + n] : 0.f;
        int off = SWZ(co*256 + ci*2);
        int dst = n*3072 + (off >> 1);
        __nv_bfloat16 h, l;
        split2(v, h, l); g_wfH[dst] = h; g_wfL[dst] = l;
    }
}

// ===================== k_conv_in: 1x1 conv -> padded NHWC ===================
__global__ __launch_bounds__(256) void k_conv_in(const float* __restrict__ x,
                                                 const float* __restrict__ w,
                                                 const float* __restrict__ bias) {
    __shared__ float Ws[32*WP];
    __shared__ float Xs[32*64];
    int tid = threadIdx.x;
    int b  = blockIdx.y;
    int p0 = blockIdx.x * 64;
    int ty = tid >> 4, tx = tid & 15;
    int cob = ty*8, pxb = tx*4;

    ACC_INIT
    for (int cb = 0; cb < CH; cb += 32) {
        __syncthreads();
        for (int idx = tid; idx < 4096; idx += 256) {
            int co = idx >> 5, c = idx & 31;
            Ws[c*WP + co] = w[co*CH + cb + c];
        }
        for (int idx = tid; idx < 2048; idx += 256) {
            int c = idx >> 6, p = idx & 63;
            Xs[c*64 + p] = x[((size_t)b*CH + cb + c)*HW + p0 + p];
        }
        __syncthreads();
#pragma unroll 8
        for (int c = 0; c < 32; c++) { GSTEP(&Xs[c*64 + pxb], &Ws[c*WP + cob]) }
    }
    float v[4][8];
#pragma unroll
    for (int k = 0; k < 4; k++)
#pragma unroll
        for (int px = 0; px < 4; px++) {
            float2 f = unp2(acc[px][k]);
            v[px][2*k] = f.x; v[px][2*k+1] = f.y;
        }
    float bb[8];
#pragma unroll
    for (int u = 0; u < 8; u++) bb[u] = __ldg(&bias[cob + u]);
#pragma unroll
    for (int px = 0; px < 4; px++) {
        int pix = p0 + pxb + px;
        int i = pix / 96, j = pix - i*96;
        size_t pbase = ((size_t)b*P98 + (i+1)*98 + (j+1))*CH + cob;
        float fv[8];
#pragma unroll
        for (int u = 0; u < 8; u++) fv[u] = v[px][u] + bb[u];
        *(float4*)&g_xp[pbase]   = make_float4(fv[0], fv[1], fv[2], fv[3]);
        *(float4*)&g_xp[pbase+4] = make_float4(fv[4], fv[5], fv[6], fv[7]);
        __nv_bfloat162 hv[4], lv[4];
#pragma unroll
        for (int u = 0; u < 4; u++) {
            __nv_bfloat16 h0,l0,h1,l1;
            split2(fv[2*u], h0, l0); split2(fv[2*u+1], h1, l1);
            hv[u].x = h0; hv[u].y = h1; lv[u].x = l0; lv[u].y = l1;
        }
        *(uint4*)&g_xpH[pbase] = *(uint4*)hv;
        *(uint4*)&g_xpL[pbase] = *(uint4*)lv;
    }
}

// ===================== MMA K=128 tap (ldmatrix, term-major): 32x32/warp =====
__device__ __forceinline__ void mma_tap(u32 sA, u32 sB, float acc[2][4][4],
                                        int pb, int cb, int lane) {
    int l15 = lane & 15;
    u32 hA = (u32)((lane >> 4) << 4);
    int rA = pb + l15;
    u32 mA = (u32)((rA & 7) << 4);
    u32 baseA0 = sA + rA*256;
    u32 baseA1 = baseA0 + 16*256;
    int rB = cb + ((lane >> 4) & 1)*8 + (lane & 7);
    u32 hB = (u32)(((lane >> 3) & 1) << 4);
    u32 mB = (u32)((rB & 7) << 4);
    u32 baseB0 = sB + rB*256;
    u32 baseB1 = baseB0 + 16*256;
#pragma unroll
    for (int ks = 0; ks < 8; ks++) {
        u32 offA = ((u32)(ks*32) + hA) ^ mA;
        u32 offB = ((u32)(ks*32) + hB) ^ mB;
        u32 ah0[4], ah1[4], al0[4], al1[4];
        ldsm4(ah0, baseA0 + offA);
        ldsm4(ah1, baseA1 + offA);
        ldsm4(al0, baseA0 + 32768 + offA);
        ldsm4(al1, baseA1 + 32768 + offA);
        u32 bh[8], bl[8];
        ldsm4(bh,     baseB0 + offB);
        ldsm4(bh + 4, baseB1 + offB);
        ldsm4(bl,     baseB0 + 32768 + offB);
        ldsm4(bl + 4, baseB1 + 32768 + offB);
        // term-major: all 8 accumulators per term -> no RAW chains
#pragma unroll
        for (int nt = 0; nt < 4; nt++) {
            MMA_BF16(acc[0][nt], ah0, bh[nt*2], bh[nt*2+1]);
            MMA_BF16(acc[1][nt], ah1, bh[nt*2], bh[nt*2+1]);
        }
#pragma unroll
        for (int nt = 0; nt < 4; nt++) {
            MMA_BF16(acc[0][nt], ah0, bl[nt*2], bl[nt*2+1]);
            MMA_BF16(acc[1][nt], ah1, bl[nt*2], bl[nt*2+1]);
        }
#pragma unroll
        for (int nt = 0; nt < 4; nt++) {
            MMA_BF16(acc[0][nt], al0, bh[nt*2], bh[nt*2+1]);
            MMA_BF16(acc[1][nt], al1, bh[nt*2], bh[nt*2+1]);
        }
    }
}

// offset-conv extra MMAs (ldmatrix, term-major): 3 n8-tiles from 24x128 tile
__device__ __forceinline__ void mma_tap_off(u32 sA, u32 sBo, float acco[2][3][4],
                                            int pb, int lane) {
    int l15 = lane & 15;
    u32 hA = (u32)((lane >> 4) << 4);
    int rA = pb + l15;
    u32 mA = (u32)((rA & 7) << 4);
    u32 baseA0 = sA + rA*256;
    u32 baseA1 = baseA0 + 16*256;
    int rB = ((lane >> 4) & 1)*8 + (lane & 7);
    u32 hB = (u32)(((lane >> 3) & 1) << 4);
    u32 mB = (u32)((rB & 7) << 4);
    u32 baseO0 = sBo + rB*256;
    int rB2 = 16 + (lane & 7);
    u32 mB2 = (u32)((rB2 & 7) << 4);
    u32 baseO2 = sBo + rB2*256;
#pragma unroll
    for (int ks = 0; ks < 8; ks++) {
        u32 offA  = ((u32)(ks*32) + hA) ^ mA;
        u32 offB  = ((u32)(ks*32) + hB) ^ mB;
        u32 offB2 = ((u32)(ks*32) + hB) ^ mB2;
        u32 ah0[4], ah1[4], al0[4], al1[4];
        ldsm4(ah0, baseA0 + offA);
        ldsm4(ah1, baseA1 + offA);
        ldsm4(al0, baseA0 + 32768 + offA);
        ldsm4(al1, baseA1 + 32768 + offA);
        u32 bh[6], bl[6];
        ldsm4(bh,     baseO0 + offB);
        ldsm2(bh + 4, baseO2 + offB2);
        ldsm4(bl,     baseO0 + 6144 + offB);
        ldsm2(bl + 4, baseO2 + 6144 + offB2);
#pragma unroll
        for (int nt = 0; nt < 3; nt++) {
            MMA_BF16(acco[0][nt], ah0, bh[nt*2], bh[nt*2+1]);
            MMA_BF16(acco[1][nt], ah1, bh[nt*2], bh[nt*2+1]);
        }
#pragma unroll
        for (int nt = 0; nt < 3; nt++) {
            MMA_BF16(acco[0][nt], ah0, bl[nt*2], bl[nt*2+1]);
            MMA_BF16(acco[1][nt], ah1, bl[nt*2], bl[nt*2+1]);
        }
#pragma unroll
        for (int nt = 0; nt < 3; nt++) {
            MMA_BF16(acco[0][nt], al0, bh[nt*2], bh[nt*2+1]);
            MMA_BF16(acco[1][nt], al1, bh[nt*2], bh[nt*2+1]);
        }
    }
}

// weight cp.async stage: 4096 x 16B granules (hi+lo), identity mapping
__device__ __forceinline__ void stage_B(u32 dstu, const __nv_bfloat16* srcH,
                                        const __nv_bfloat16* srcL, int tid) {
    const char* sh = (const char*)srcH;
    const char* sl = (const char*)srcL;
    for (int i2 = tid; i2 < 2048; i2 += TMM) {
        CP16(dstu + i2*16,         sh + i2*16);
        CP16(dstu + 32768 + i2*16, sl + i2*16);
    }
}

// A tile cp.async stage for std branch (shifted window from padded buffer)
__device__ __forceinline__ void stage_A_std(u32 abase, int b, int p0, int n, int tid) {
    int di = n/3 - 1, dj = n%3 - 1;
    const char* sh = (const char*)(g_xpH + (size_t)b*P98*CH);
    const char* sl = (const char*)(g_xpL + (size_t)b*P98*CH);
    for (int idx = tid; idx < 2048; idx += TMM) {
        int px = idx >> 4, g16 = idx & 15;
        int pix = p0 + px;
        int i = pix / 96, j = pix - i*96;
        size_t src = ((size_t)((i+1+di)*98 + (j+1+dj))*CH)*2 + g16*16;
        u32 dst = abase + SWZ(px*256 + g16*16);
        CP16(dst, sh + src);
        CP16(dst + 32768, sl + src);
    }
}

// ===================== k_tstd: std 3x3 branch + fused offset conv ===========
__global__ __launch_bounds__(TMM) void k_tstd(const float* __restrict__ bstd,
                                              const float* __restrict__ bn2,
                                              const float* __restrict__ boff) {
    extern __shared__ char smem[];
    u32 sb = smem_to_u32(smem);
    int tid = threadIdx.x, wid = tid >> 5, lane = tid & 31;
    int g = lane >> 2, t = lane & 3;
    int wm = wid & 3, wn = wid >> 2;
    int pb = wm*32, cb = wn*32;
    int tile = blockIdx.x, b = blockIdx.y;
    int p0 = tile * 128;

    float acc[2][4][4];
    float acco[2][3][4];
#pragma unroll
    for (int i = 0; i < 2; i++) {
#pragma unroll
        for (int j = 0; j < 4; j++)
#pragma unroll
            for (int k = 0; k < 4; k++) acc[i][j][k] = 0.f;
#pragma unroll
        for (int j = 0; j < 3; j++)
#pragma unroll
            for (int k = 0; k < 4; k++) acco[i][j][k] = 0.f;
    }

    // prologue: A(0)+Boff(0) group, then B(0) group
    stage_A_std(sb + TS_A0, b, p0, 0, tid);
    if (tid < 384) {
        CP16(sb + TS_BO0 + tid*16,        ((const char*)g_wfH) + tid*16);
        CP16(sb + TS_BO0 + 6144 + tid*16, ((const char*)g_wfL) + tid*16);
    }
    CP_COMMIT();
    stage_B(sb + TS_B, g_wsH, g_wsL, tid);
    CP_COMMIT();

    for (int n = 0; n < 9; n++) {
        CP_WAIT0();
        __syncthreads();                  // A(n), Boff(n), B(n) resident
        if (n < 8) {                      // prefetch A(n+1)+Boff(n+1) under MMA(n)
            u32 anext = sb + (((n+1)&1) ? TS_A1 : TS_A0);
            stage_A_std(anext, b, p0, n+1, tid);
            u32 bonext = sb + (((n+1)&1) ? TS_BO1 : TS_BO0);
            if (tid < 384) {
                CP16(bonext + tid*16,        ((const char*)g_wfH) + (size_t)(n+1)*6144 + tid*16);
                CP16(bonext + 6144 + tid*16, ((const char*)g_wfL) + (size_t)(n+1)*6144 + tid*16);
            }
            CP_COMMIT();
        }
        u32 sA = sb + ((n&1) ? TS_A1 : TS_A0);
        mma_tap(sA, sb + TS_B, acc, pb, cb, lane);
        if (wn == 3) mma_tap_off(sA, sb + ((n&1) ? TS_BO1 : TS_BO0), acco, pb, lane);
        __syncthreads();                  // all warps done reading B(n)
        if (n < 8) {
            stage_B(sb + TS_B, g_wsH + (n+1)*16384, g_wsL + (n+1)*16384, tid);
            CP_COMMIT();
        }
    }
    const float* xpb = g_xp + (size_t)b*P98*CH;
    char* oH = (char*)(g_a2H + (size_t)(b*NTILES + tile)*16384);
    char* oL = (char*)(g_a2L + (size_t)(b*NTILES + tile)*16384);
#pragma unroll
    for (int mt = 0; mt < 2; mt++)
#pragma unroll
        for (int nt = 0; nt < 4; nt++) {
            int row = pb + mt*16 + g;
            int co  = cb + nt*8 + 2*t;
            float i0 = __ldg(&bn2[co]) / sqrtf(__ldg(&bn2[384+co]) + EPSBN);
            float a0 = __ldg(&bn2[128+co]) - __ldg(&bn2[256+co]) * i0;
            float i1 = __ldg(&bn2[co+1]) / sqrtf(__ldg(&bn2[385+co]) + EPSBN);
            float a1 = __ldg(&bn2[129+co]) - __ldg(&bn2[257+co]) * i1;
            float b0v = __ldg(&bstd[co]), b1v = __ldg(&bstd[co+1]);
            const float* d = acc[mt][nt];
            int pix0 = p0 + row, pix1 = p0 + row + 8;
            int i_0 = pix0/96, j_0 = pix0 - i_0*96;
            int i_1 = pix1/96, j_1 = pix1 - i_1*96;
            float2 xc0 = *(const float2*)(xpb + (size_t)((i_0+1)*98 + j_0+1)*CH + co);
            float2 xc1 = *(const float2*)(xpb + (size_t)((i_1+1)*98 + j_1+1)*CH + co);
            float f00 = fmaxf((d[0] + b0v)*i0 + a0, 0.f) + xc0.x;
            float f01 = fmaxf((d[1] + b1v)*i1 + a1, 0.f) + xc0.y;
            float f10 = fmaxf((d[2] + b0v)*i0 + a0, 0.f) + xc1.x;
            float f11 = fmaxf((d[3] + b1v)*i1 + a1, 0.f) + xc1.y;
            __nv_bfloat16 h0,l0,h1,l1;
            split2(f00,h0,l0); split2(f01,h1,l1);
            int off = SWZ(row*256 + co*2);
            __nv_bfloat162 hv; hv.x=h0; hv.y=h1;
            __nv_bfloat162 lv; lv.x=l0; lv.y=l1;
            *(__nv_bfloat162*)(oH + off) = hv;
            *(__nv_bfloat162*)(oL + off) = lv;
            split2(f10,h0,l0); split2(f11,h1,l1);
            off = SWZ((row+8)*256 + co*2);
            hv.x=h0; hv.y=h1; lv.x=l0; lv.y=l1;
            *(__nv_bfloat162*)(oH + off) = hv;
            *(__nv_bfloat162*)(oL + off) = lv;
        }
    if (wn == 3) {
#pragma unroll
        for (int mt = 0; mt < 2; mt++)
#pragma unroll
            for (int nt = 0; nt < 3; nt++) {
                int co = nt*8 + 2*t;
                if (co < 18) {
                    int row = pb + mt*16 + g;
                    const float* d = acco[mt][nt];
                    g_off[(size_t)(b*18 + co  )*HW + p0 + row]     = d[0] + __ldg(&boff[co]);
                    g_off[(size_t)(b*18 + co+1)*HW + p0 + row]     = d[1] + __ldg(&boff[co+1]);
                    g_off[(size_t)(b*18 + co  )*HW + p0 + row + 8] = d[2] + __ldg(&boff[co]);
                    g_off[(size_t)(b*18 + co+1)*HW + p0 + row + 8] = d[3] + __ldg(&boff[co+1]);
                }
            }
    }
}

// ===================== deform gather: fill one A buffer for tap n ===========
__device__ __forceinline__ void gather_tap(char* sA, const float* xpb, int b, int p0,
                                           int n, int wid, int lane) {
    float dnx = (float)(n/3 - 1), dny = (float)(n%3 - 1);
#pragma unroll 4
    for (int k = 0; k < 8; k++) {
        int px = wid*8 + k;
        int pix = p0 + px;
        int i = pix / 96, j = pix - i*96;
        float ox = __ldg(&g_off[(size_t)(b*18 + n    )*HW + pix]);
        float oy = __ldg(&g_off[(size_t)(b*18 + n + 9)*HW + pix]);
        float pfx = ox + dnx + (float)(i + 1);
        float pfy = oy + dny + (float)(j + 1);
        float qx = floorf(pfx), qy = floorf(pfy);
        float ltx = fminf(fmaxf(qx,       0.f), 97.f);
        float lty = fminf(fmaxf(qy,       0.f), 97.f);
        float rbx = fminf(fmaxf(qx + 1.f, 0.f), 97.f);
        float rby = fminf(fmaxf(qy + 1.f, 0.f), 97.f);
        float pcx = fminf(fmaxf(pfx, 0.f), 97.f);
        float pcy = fminf(fmaxf(pfy, 0.f), 97.f);
        float glt = (1.f + (ltx - pcx)) * (1.f + (lty - pcy));
        float grb = (1.f - (rbx - pcx)) * (1.f - (rby - pcy));
        float glb = (1.f + (ltx - pcx)) * (1.f - (rby - pcy));
        float grt = (1.f - (rbx - pcx)) * (1.f + (lty - pcy));
        int ix0 = (int)ltx, iy0 = (int)lty, ix1 = (int)rbx, iy1 = (int)rby;
        const float* plt = xpb + (size_t)(ix0*98 + iy0)*CH;
        const float* prb = xpb + (size_t)(ix1*98 + iy1)*CH;
        const float* plb = xpb + (size_t)(ix0*98 + iy1)*CH;
        const float* prt = xpb + (size_t)(ix1*98 + iy0)*CH;
#pragma unroll
        for (int it = 0; it < 2; it++) {
            int ci0 = it*64 + lane*2;
            float2 a2 = *(const float2*)(plt + ci0);
            float2 b2 = *(const float2*)(prb + ci0);
            float2 c2 = *(const float2*)(plb + ci0);
            float2 d2 = *(const float2*)(prt + ci0);
            float v0 = glt*a2.x + grb*b2.x + glb*c2.x + grt*d2.x;
            float v1 = glt*a2.y + grb*b2.y + glb*c2.y + grt*d2.y;
            __nv_bfloat16 h0, l0, h1, l1;
            split2(v0, h0, l0); split2(v1, h1, l1);
            int off = SWZ(px*256 + ci0*2);
            __nv_bfloat162 hv; hv.x = h0; hv.y = h1;
            __nv_bfloat162 lv; lv.x = l0; lv.y = l1;
            *(__nv_bfloat162*)(sA + off) = hv;
            *(__nv_bfloat162*)(sA + 32768 + off) = lv;
        }
    }
}

// ===================== k_tdef: deform branch (pipelined gather) =============
__global__ __launch_bounds__(TMM) void k_tdef(const float* __restrict__ bdef,
                                              const float* __restrict__ bn1) {
    extern __shared__ char smem[];
    u32 sb = smem_to_u32(smem);
    int tid = threadIdx.x, wid = tid >> 5, lane = tid & 31;
    int g = lane >> 2, t = lane & 3;
    int wm = wid & 3, wn = wid >> 2;
    int pb = wm*32, cb = wn*32;
    int tile = blockIdx.x, b = blockIdx.y;
    int p0 = tile * 128;

    float acc[2][4][4];
#pragma unroll
    for (int i = 0; i < 2; i++)
#pragma unroll
        for (int j = 0; j < 4; j++)
#pragma unroll
            for (int k = 0; k < 4; k++) acc[i][j][k] = 0.f;

    const float* xpb = g_xp + (size_t)b*P98*CH;

    // prologue: B(0) cp.async; gather A(0)
    stage_B(sb + TD_B, g_wdH, g_wdL, tid);
    CP_COMMIT();
    gather_tap(smem + TD_A0, xpb, b, p0, 0, wid, lane);

    for (int n = 0; n < 9; n++) {
        CP_WAIT0();
        __syncthreads();                  // A(n) gathered by all, B(n) resident
        if (n < 8)                        // gather A(n+1) overlaps other warps' MMA(n)
            gather_tap(smem + (((n+1)&1) ? TD_A1 : TD_A0), xpb, b, p0, n+1, wid, lane);
        mma_tap(sb + ((n&1) ? TD_A1 : TD_A0), sb + TD_B, acc, pb, cb, lane);
        __syncthreads();                  // all warps done with B(n) + gathers done
        if (n < 8) {
            stage_B(sb + TD_B, g_wdH + (n+1)*16384, g_wdL + (n+1)*16384, tid);
            CP_COMMIT();
        }
    }
    char* oH = (char*)(g_a1H + (size_t)(b*NTILES + tile)*16384);
    char* oL = (char*)(g_a1L + (size_t)(b*NTILES + tile)*16384);
#pragma unroll
    for (int mt = 0; mt < 2; mt++)
#pragma unroll
        for (int nt = 0; nt < 4; nt++) {
            int row = pb + mt*16 + g;
            int co  = cb + nt*8 + 2*t;
            float i0 = __ldg(&bn1[co]) / sqrtf(__ldg(&bn1[384+co]) + EPSBN);
            float a0 = __ldg(&bn1[128+co]) - __ldg(&bn1[256+co]) * i0;
            float i1 = __ldg(&bn1[co+1]) / sqrtf(__ldg(&bn1[385+co]) + EPSBN);
            float a1 = __ldg(&bn1[129+co]) - __ldg(&bn1[257+co]) * i1;
            float b0v = __ldg(&bdef[co]), b1v = __ldg(&bdef[co+1]);
            const float* d = acc[mt][nt];
            float f00 = fmaxf((d[0] + b0v)*i0 + a0, 0.f);
            float f01 = fmaxf((d[1] + b1v)*i1 + a1, 0.f);
            float f10 = fmaxf((d[2] + b0v)*i0 + a0, 0.f);
            float f11 = fmaxf((d[3] + b1v)*i1 + a1, 0.f);
            __nv_bfloat16 h0,l0,h1,l1;
            split2(f00,h0,l0); split2(f01,h1,l1);
            int off = SWZ(row*256 + co*2);
            __nv_bfloat162 hv; hv.x=h0; hv.y=h1;
            __nv_bfloat162 lv; lv.x=l0; lv.y=l1;
            *(__nv_bfloat162*)(oH + off) = hv;
            *(__nv_bfloat162*)(oL + off) = lv;
            split2(f10,h0,l0); split2(f11,h1,l1);
            off = SWZ((row+8)*256 + co*2);
            hv.x=h0; hv.y=h1; lv.x=l0; lv.y=l1;
            *(__nv_bfloat162*)(oH + off) = hv;
            *(__nv_bfloat162*)(oL + off) = lv;
        }
}

// ===================== k_tout: final 1x1 conv ===============================
__global__ __launch_bounds__(TMM) void k_tout(const float* __restrict__ bias,
                                              float* __restrict__ out) {
    extern __shared__ char smem[];
    u32 sb = smem_to_u32(smem);
    int tid = threadIdx.x, wid = tid >> 5, lane = tid & 31;
    int g = lane >> 2, t = lane & 3;
    int wm = wid & 3, wn = wid >> 2;
    int pb = wm*32, cb = wn*32;
    int tile = blockIdx.x, b = blockIdx.y, z = blockIdx.z;
    int p0 = tile * 128;

    float acc[2][4][4];
#pragma unroll
    for (int i = 0; i < 2; i++)
#pragma unroll
        for (int j = 0; j < 4; j++)
#pragma unroll
            for (int k = 0; k < 4; k++) acc[i][j][k] = 0.f;

    for (int kc = 0; kc < 2; kc++) {
        __syncthreads();
        {
            const char* wh = (const char*)(g_woH + (z*2 + kc)*16384);
            const char* wl = (const char*)(g_woL + (z*2 + kc)*16384);
            const char* ah = (const char*)((kc ? g_a2H : g_a1H) + (size_t)(b*NTILES + tile)*16384);
            const char* al = (const char*)((kc ? g_a2L : g_a1L) + (size_t)(b*NTILES + tile)*16384);
            for (int i2 = tid; i2 < 2048; i2 += TMM) {
                CP16(sb + TO_A + i2*16,         ah + i2*16);
                CP16(sb + TO_A + 32768 + i2*16, al + i2*16);
                CP16(sb + TO_B + i2*16,         wh + i2*16);
                CP16(sb + TO_B + 32768 + i2*16, wl + i2*16);
            }
            CP_COMMIT();
            CP_WAIT0();
        }
        __syncthreads();
        mma_tap(sb + TO_A, sb + TO_B, acc, pb, cb, lane);
    }
#pragma unroll
    for (int mt = 0; mt < 2; mt++)
#pragma unroll
        for (int nt = 0; nt < 4; nt++) {
            int row = p0 + pb + mt*16 + g;
            int co  = z*128 + cb + nt*8 + 2*t;
            float b0v = __ldg(&bias[co]), b1v = __ldg(&bias[co+1]);
            const float* d = acc[mt][nt];
            out[((size_t)(b*256 + co  ))*HW + row]     = d[0] + b0v;
            out[((size_t)(b*256 + co+1))*HW + row]     = d[1] + b1v;
            out[((size_t)(b*256 + co  ))*HW + row + 8] = d[2] + b0v;
            out[((size_t)(b*256 + co+1))*HW + row + 8] = d[3] + b1v;
        }
}

// ===================== launch ===============================================
extern "C" void kernel_launch(void* const* d_in, const int* in_sizes, int n_in,
                              void* d_out, int out_size) {
    const float* x     = (const float*)d_in[0];
    const float* w_in  = (const float*)d_in[1];
    const float* b_in  = (const float*)d_in[2];
    const float* w_off = (const float*)d_in[3];
    const float* b_off = (const float*)d_in[4];
    const float* w_def = (const float*)d_in[5];
    const float* b_def = (const float*)d_in[6];
    const float* bn1   = (const float*)d_in[7];
    const float* w_std = (const float*)d_in[8];
    const float* b_std = (const float*)d_in[9];
    const float* bn2   = (const float*)d_in[10];
    const float* w_out = (const float*)d_in[11];
    const float* b_out = (const float*)d_in[12];
    float* out = (float*)d_out;

    cudaFuncSetAttribute(k_tdef, cudaFuncAttributeMaxDynamicSharedMemorySize, SMEM_TD);
    cudaFuncSetAttribute(k_tstd, cudaFuncAttributeMaxDynamicSharedMemorySize, SMEM_TS);
    cudaFuncSetAttribute(k_tout, cudaFuncAttributeMaxDynamicSharedMemorySize, SMEM_TO);

    k_zero   <<<2048, 256>>>();
    k_prep   <<<940, 256>>>(w_def, w_std, w_out, w_off);
    k_conv_in<<<dim3(144, BATCH), 256>>>(x, w_in, b_in);
    k_tstd   <<<dim3(NTILES, BATCH), TMM, SMEM_TS>>>(b_std, bn2, b_off);
    k_tdef   <<<dim3(NTILES, BATCH), TMM, SMEM_TD>>>(b_def, bn1);
    k_tout   <<<dim3(NTILES, BATCH, 2), TMM, SMEM_TO>>>(b_out, out);
}